// round 12
// baseline (speedup 1.0000x reference)
#include <cuda_runtime.h>
#include <cstdint>

#define NB 2
#define NN 32768
#define NC 64
#define NPT (NB * NN)
#define NBLK2 2080

typedef unsigned long long ull;

__device__ __forceinline__ ull pk2(float x, float y) {
    ull r; asm("mov.b64 %0, {%1,%2};" : "=l"(r) : "f"(x), "f"(y)); return r;
}
__device__ __forceinline__ float2 unpk(ull a) {
    float2 v; asm("mov.b64 {%0,%1}, %2;" : "=f"(v.x), "=f"(v.y) : "l"(a)); return v;
}
__device__ __forceinline__ ull f2fma(ull a, ull b, ull c) {
    ull d; asm("fma.rn.f32x2 %0, %1, %2, %3;" : "=l"(d) : "l"(a), "l"(b), "l"(c)); return d;
}

// ------------------------- device scratch (no allocs) -------------------------
__device__ __align__(16) float d_fT[NPT * NC];
__device__ __align__(16) float d_x[NPT * NC];
__device__ unsigned char d_cls[NPT];
__device__ int d_seq[16 * 16];
__device__ __align__(16) float d_A[64 * 64];
__device__ float d_gvec[64];
__device__ float d_c0;
__device__ __align__(16) float d_PR[32 * 64 * 32];  // [cls][c][i32]
__device__ __align__(16) float d_Vw[32 * 16 * 64];  // [cls][i][pair] interleaved (c,c+32)
__device__ float d_pb[32 * 32];
__device__ float d_m[32 * 16];
__device__ float d_S16[32 * 16];
__device__ float d_Eii[32 * 16];
__device__ float d_psum[NBLK2 * 64];   // [bucket][c]
__device__ float d_psq[NBLK2 * 64];
__device__ float d_scale[64];
__device__ float d_shift[64];
// sorting
__device__ int d_done;
__device__ int d_cnt[32];
__device__ int d_base[32];
__device__ int d_pos[32];
__device__ int d_ecum[33];
__device__ int d_nbkt;
__device__ int d_order[NPT];
__device__ int d_bcls[NBLK2];
__device__ int d_bstart[NBLK2];
__device__ int d_bn[NBLK2];

// ------------------------- kT: transpose feature -> point-major (+zero counters) -------------------------
__global__ void kT(const float* __restrict__ feat) {
    int bI = blockIdx.x;
    int b = bI >> 10;
    int n0 = (bI & 1023) * 32;
    __shared__ __align__(16) float sh[64 * 33];
    int t = threadIdx.x;
    if (bI == 0 && t < 32) d_cnt[t] = 0;
    if (bI == 0 && t == 32) d_done = 0;
#pragma unroll
    for (int k = 0; k < 8; k++) {
        int idx = t + k * 256;
        int c = idx >> 5, col = idx & 31;
        sh[c * 33 + col] = feat[(b * 64 + c) * NN + n0 + col];
    }
    __syncthreads();
    int p = t >> 3, c8 = (t & 7) * 8;
    float4 v0, v1;
    v0.x = sh[(c8 + 0) * 33 + p]; v0.y = sh[(c8 + 1) * 33 + p];
    v0.z = sh[(c8 + 2) * 33 + p]; v0.w = sh[(c8 + 3) * 33 + p];
    v1.x = sh[(c8 + 4) * 33 + p]; v1.y = sh[(c8 + 5) * 33 + p];
    v1.z = sh[(c8 + 6) * 33 + p]; v1.w = sh[(c8 + 7) * 33 + p];
    float* dst = &d_fT[(b * NN + n0 + p) * 64 + c8];
    *(float4*)dst = v0;
    *(float4*)(dst + 4) = v1;
}

// ------------------------- k0: argmax2 class + histogram + (last block) scan + walk sequences -------------------------
__global__ void k0(const int* __restrict__ knn) {
    int w = threadIdx.x >> 5, lane = threadIdx.x & 31;
    int pt = blockIdx.x * 8 + w;
    int b = pt >> 15, n = pt & 32767;
    __shared__ __align__(16) float selfv[8][64];
    __shared__ float simsh[8][16];
    __shared__ int h[32];
    __shared__ int shLast;
    if (threadIdx.x < 32) h[threadIdx.x] = 0;

    float2 fv = *(const float2*)&d_fT[pt * 64 + lane * 2];
    selfv[w][lane * 2] = fv.x;
    selfv[w][lane * 2 + 1] = fv.y;
    __syncthreads();

    int j = lane & 15, half = lane >> 4;
    int nb = __ldg(&knn[(b * NN + n) * 16 + j]);
    const float* nrow = &d_fT[(b * NN + nb) * 64 + half * 32];
    const float* srow = &selfv[w][half * 32];
    float part = 0.f;
#pragma unroll
    for (int c = 0; c < 32; c += 4) {
        float4 nv = *(const float4*)(nrow + c);
        float4 sv = *(const float4*)(srow + c);
        part += nv.x * sv.x + nv.y * sv.y + nv.z * sv.z + nv.w * sv.w;
    }
    float sim = part + __shfl_xor_sync(0xffffffffu, part, 16);
    if (half == 0) simsh[w][j] = sim;
    __syncwarp();

    if (lane == 0) {
        float v1 = -1e30f; int i1 = 0;
        for (int jj = 0; jj < 16; jj++) {
            float v = simsh[w][jj];
            if (v > v1) { v1 = v; i1 = jj; }
        }
        float v2 = -1e30f; int i2 = 0;
        for (int jj = 0; jj < 16; jj++) {
            if (jj == i1) continue;
            float v = simsh[w][jj];
            if (v > v2) { v2 = v; i2 = jj; }
        }
        d_cls[pt] = (unsigned char)i2;
        atomicAdd(&h[(b << 4) | i2], 1);
    }
    __syncthreads();
    if (threadIdx.x < 32 && h[threadIdx.x]) atomicAdd(&d_cnt[threadIdx.x], h[threadIdx.x]);

    // ---- last-block-done: run scan + walk sequences ----
    __threadfence();
    __syncthreads();
    if (threadIdx.x == 0)
        shLast = (atomicAdd(&d_done, 1) == (int)gridDim.x - 1) ? 1 : 0;
    __syncthreads();
    if (shLast && threadIdx.x < 32) {
        int t = threadIdx.x;
        int cnt = atomicAdd(&d_cnt[t], 0);    // L2-coherent read
        int x = cnt;
#pragma unroll
        for (int off = 1; off < 32; off <<= 1) {
            int y = __shfl_up_sync(0xffffffffu, x, off);
            if (t >= off) x += y;
        }
        int ex = x - cnt;
        d_base[t] = ex;
        d_pos[t] = ex;
        int ent = (cnt + 31) >> 5;
        int z = ent;
#pragma unroll
        for (int off = 1; off < 32; off <<= 1) {
            int y = __shfl_up_sync(0xffffffffu, z, off);
            if (t >= off) z += y;
        }
        int eex = z - ent;
        d_ecum[t] = eex;
        if (t == 31) { d_ecum[32] = z; d_nbkt = z; }
        if (t < 16) {
            int cur = t;
            d_seq[t * 16] = t;
            for (int s = 1; s < 16; s++) {
                cur = (int)__ldcg(&d_cls[cur]);
                d_seq[t * 16 + s] = cur;
            }
        }
    }
}

// ------------------------- kPre: blocks 0-31 class tables, 32-63 A matrix + bucket fill, 64-127 scatter (li==0) -------------------------
__global__ void __launch_bounds__(256) kPre(const float* __restrict__ Wq, const float* __restrict__ bq,
                                            const float* __restrict__ Wk, const float* __restrict__ bk,
                                            const float* __restrict__ Wv, const float* __restrict__ bv, int li) {
    const float* wq = Wq + li * 4096;
    const float* wk = Wk + li * 4096;
    const float* wv = Wv + li * 4096;
    const float* bqv = bq + li * 64;
    const float* bkv = bk + li * 64;
    const float* bvv = bv + li * 64;
    int t = threadIdx.x;

    if (blockIdx.x >= 64) {
        // ---- scatter with block-aggregated atomics (only layer 0) ----
        if (li != 0) return;
        __shared__ int hcnt[32], hbase[32];
        if (t < 32) hcnt[t] = 0;
        __syncthreads();
        int sb = blockIdx.x - 64;
        int mycls[4], myrank[4];
#pragma unroll
        for (int k = 0; k < 4; k++) {
            int pt = sb * 1024 + k * 256 + t;
            int cls = ((pt >> 15) << 4) | (int)d_cls[pt];
            mycls[k] = cls;
            myrank[k] = atomicAdd(&hcnt[cls], 1);
        }
        __syncthreads();
        if (t < 32 && hcnt[t]) hbase[t] = atomicAdd(&d_pos[t], hcnt[t]);
        __syncthreads();
#pragma unroll
        for (int k = 0; k < 4; k++) {
            int pt = sb * 1024 + k * 256 + t;
            d_order[hbase[mycls[k]] + myrank[k]] = pt;
        }
        return;
    }

    __shared__ __align__(16) float shA[64 * 68];
    __shared__ __align__(16) float shB[64 * 68];
    __shared__ float Wf[1024], Qw[1024], Kw[1024];
    __shared__ float simm[256];

    if (blockIdx.x >= 32) {
        // ---- bucket table fill (65 entries per block) ----
        int nbkt = d_nbkt;
        int ebase = (blockIdx.x - 32) * 65;
        if (t < 65) {
            int e = ebase + t;
            if (e < NBLK2) {
                if (e < nbkt) {
                    int c = 0;
                    while (c < 31 && d_ecum[c + 1] <= e) c++;
                    int local = e - d_ecum[c];
                    int cnt = d_cnt[c];
                    d_bcls[e] = c;
                    d_bstart[e] = d_base[c] + local * 32;
                    int rem = cnt - local * 32;
                    d_bn[e] = rem < 32 ? rem : 32;
                } else {
                    d_bcls[e] = -1;
                }
            }
        }
        // ---- A = Wq^T Wk ----
        for (int idx = t; idx < 4096; idx += 256) {
            shA[idx] = __ldg(&wq[idx]);
            shB[idx] = __ldg(&wk[idx]);
        }
        __syncthreads();
        int base = (blockIdx.x - 32) * 128;
        if (t < 128) {
            int e = base + t;
            int c = e >> 6, cp = e & 63;
            float a = 0.f;
#pragma unroll 8
            for (int d = 0; d < 64; d++) a += shA[d * 64 + c] * shB[d * 64 + cp];
            d_A[e] = a;
        }
        if (blockIdx.x == 32) {
            if (t >= 128 && t < 192) {
                int c = t - 128;
                float g = 0.f;
                for (int d = 0; d < 64; d++) g += __ldg(&bqv[d]) * shB[d * 64 + c] + __ldg(&bkv[d]) * shA[d * 64 + c];
                d_gvec[c] = g;
            }
            if (t == 255) {
                float c0 = 0.f;
                for (int d = 0; d < 64; d++) c0 += __ldg(&bqv[d]) * __ldg(&bkv[d]);
                d_c0 = c0;
            }
        }
        return;
    }

    int cls = blockIdx.x;
    int b = cls >> 4, s = cls & 15;

    for (int idx = t; idx < 4096; idx += 256) {
        int d = idx >> 6, c = idx & 63;
        shA[c * 68 + d] = __ldg(&wq[idx]);
        shB[c * 68 + d] = __ldg(&wk[idx]);
    }
    for (int idx = t; idx < 1024; idx += 256) {
        int i = idx >> 6, c = idx & 63;
        int p = d_seq[s * 16 + i];
        Wf[idx] = d_fT[(b * NN + p) * 64 + c];
    }
    __syncthreads();

    for (int idx = t; idx < 1024; idx += 256) {
        int i = idx >> 6, d = idx & 63;
        float aq = __ldg(&bqv[d]), ak = __ldg(&bkv[d]), av = __ldg(&bvv[d]);
#pragma unroll
        for (int c = 0; c < 64; c += 4) {
            float4 q4 = __ldg((const float4*)&wq[d * 64 + c]);
            float4 k4 = __ldg((const float4*)&wk[d * 64 + c]);
            float4 v4 = __ldg((const float4*)&wv[d * 64 + c]);
            float4 wf = *(const float4*)&Wf[i * 64 + c];
            aq += q4.x * wf.x + q4.y * wf.y + q4.z * wf.z + q4.w * wf.w;
            ak += k4.x * wf.x + k4.y * wf.y + k4.z * wf.z + k4.w * wf.w;
            av += v4.x * wf.x + v4.y * wf.y + v4.z * wf.z + v4.w * wf.w;
        }
        Qw[idx] = aq;
        Kw[idx] = ak;
        int pos = (d < 32) ? (2 * d) : (2 * (d - 32) + 1);
        d_Vw[cls * 1024 + i * 64 + pos] = av;
    }
    __syncthreads();

    for (int idx = t; idx < 1024; idx += 256) {
        int i = idx >> 6, c = idx & 63;
        float ap = 0.f, ar = 0.f;
#pragma unroll
        for (int d = 0; d < 64; d += 4) {
            float4 kk = *(const float4*)&shB[c * 68 + d];
            float4 qq = *(const float4*)&shA[c * 68 + d];
            float4 qw = *(const float4*)&Qw[i * 64 + d];
            float4 kw = *(const float4*)&Kw[i * 64 + d];
            ap += qw.x * kk.x + qw.y * kk.y + qw.z * kk.z + qw.w * kk.w;
            ar += kw.x * qq.x + kw.y * qq.y + kw.z * qq.z + kw.w * qq.w;
        }
        d_PR[cls * 2048 + c * 32 + i] = ap;
        d_PR[cls * 2048 + c * 32 + 16 + i] = ar;
    }
    if (t < 32) {
        int i = t & 15;
        float acc = 0.f;
        if (t < 16) { for (int d = 0; d < 64; d++) acc += Qw[i * 64 + d] * __ldg(&bkv[d]); }
        else        { for (int d = 0; d < 64; d++) acc += Kw[i * 64 + d] * __ldg(&bqv[d]); }
        d_pb[cls * 32 + t] = acc;
    }
    {
        int i = t >> 4, jj = t & 15;
        float a = 0.f;
        for (int d = 0; d < 64; d++) a += Qw[i * 64 + d] * Kw[jj * 64 + d];
        simm[t] = a;
    }
    __syncthreads();
    if (t < 16) {
        float m = -1e30f;
        for (int jj = 0; jj < 16; jj++) m = fmaxf(m, simm[t * 16 + jj]);
        float S = 0.f;
        for (int jj = 0; jj < 16; jj++) S += __expf(simm[t * 16 + jj] - m);
        d_m[cls * 16 + t] = m;
        d_S16[cls * 16 + t] = S;
        d_Eii[cls * 16 + t] = __expf(simm[t * 16 + t] - m);
    }
}

// ------------------------- k2: q=8, two-pass matvec (lower regs), fused BN partials -------------------------
__global__ void __launch_bounds__(128, 4) k2(const float* __restrict__ Wv,
                                             const float* __restrict__ bv, int li) {
    int cls = __ldg(&d_bcls[blockIdx.x]);
    if (cls < 0) return;
    int bstart = __ldg(&d_bstart[blockIdx.x]);
    int bn = __ldg(&d_bn[blockIdx.x]);

    __shared__ __align__(16) float As[64 * 68];
    __shared__ __align__(16) float Ws[64 * 68];
    __shared__ __align__(16) float sfv[4][8][64];
    __shared__ float red[4][4][32];
    int t = threadIdx.x;
    const float* wv = Wv + li * 4096;

    for (int idx = t; idx < 4096; idx += 128) {
        int r = idx >> 6, c = idx & 63;
        As[r * 68 + c] = d_A[idx];
        Ws[r * 68 + c] = __ldg(&wv[idx]);
    }
    __syncthreads();

    int wid = t >> 5, lane = t & 31;

    int pts[8];
#pragma unroll
    for (int q = 0; q < 8; q++) {
        int idx = wid * 8 + q;
        int src = bstart + (idx < bn ? idx : 0);
        int pt = __ldg(&d_order[src]);
        pts[q] = pt;
        float2 fv = *(const float2*)&d_fT[pt * 64 + lane * 2];
        sfv[wid][q][lane * 2] = fv.x;
        sfv[wid][q][lane * 2 + 1] = fv.y;
    }
    __syncwarp();

    float pbl = __ldg(&d_pb[cls * 32 + lane]);
    float mi = 0.f, Si = 0.f, Ei = 0.f;
    if (lane < 16) {
        mi = __ldg(&d_m[cls * 16 + lane]);
        Si = __ldg(&d_S16[cls * 16 + lane]);
        Ei = __ldg(&d_Eii[cls * 16 + lane]);
    }
    float gl0 = __ldg(&d_gvec[lane]);
    float gl1 = __ldg(&d_gvec[lane + 32]);
    float c0v = d_c0;
    float bv0 = __ldg(&bv[li * 64 + lane]);
    float bv1 = __ldg(&bv[li * 64 + lane + 32]);

    const float* A0 = &As[lane * 68];
    const float* A1 = &As[(lane + 32) * 68];
    const float* W0 = &Ws[lane * 68];
    const float* W1 = &Ws[(lane + 32) * 68];

    // ---- u-pass: u = A.f ----
    float qk[8];
    {
        ull u0[8], u1[8];
#pragma unroll
        for (int q = 0; q < 8; q++) { u0[q] = 0; u1[q] = 0; }
#pragma unroll
        for (int c = 0; c < 64; c += 4) {
            float4 a0 = *(const float4*)(A0 + c);
            float4 a1 = *(const float4*)(A1 + c);
            ull a0l = pk2(a0.x, a0.y), a0h = pk2(a0.z, a0.w);
            ull a1l = pk2(a1.x, a1.y), a1h = pk2(a1.z, a1.w);
#pragma unroll
            for (int q = 0; q < 8; q++) {
                float4 f = *(const float4*)&sfv[wid][q][c];
                ull fl = pk2(f.x, f.y), fh = pk2(f.z, f.w);
                u0[q] = f2fma(a0l, fl, u0[q]); u0[q] = f2fma(a0h, fh, u0[q]);
                u1[q] = f2fma(a1l, fl, u1[q]); u1[q] = f2fma(a1h, fh, u1[q]);
            }
        }
#pragma unroll
        for (int q = 0; q < 8; q++) {
            float2 uu0 = unpk(u0[q]), uu1 = unpk(u1[q]);
            float fl0 = sfv[wid][q][lane];
            float fl1 = sfv[wid][q][lane + 32];
            float part = (uu0.x + uu0.y + gl0) * fl0 + (uu1.x + uu1.y + gl1) * fl1;
#pragma unroll
            for (int off = 16; off; off >>= 1) part += __shfl_xor_sync(0xffffffffu, part, off);
            qk[q] = part + c0v;
        }
    }

    // ---- cross terms + softmax diagonals ----
    const float* PRb = &d_PR[cls * 2048];
    float dotq[8];
#pragma unroll
    for (int q = 0; q < 8; q++) dotq[q] = pbl;
#pragma unroll 4
    for (int c = 0; c < 64; c += 4) {
        float p0 = __ldg(&PRb[c * 32 + lane]);
        float p1 = __ldg(&PRb[(c + 1) * 32 + lane]);
        float p2 = __ldg(&PRb[(c + 2) * 32 + lane]);
        float p3 = __ldg(&PRb[(c + 3) * 32 + lane]);
#pragma unroll
        for (int q = 0; q < 8; q++) {
            float4 f = *(const float4*)&sfv[wid][q][c];
            dotq[q] += p0 * f.x + p1 * f.y + p2 * f.z + p3 * f.w;
        }
    }

    float dval[8], d16[8];
#pragma unroll
    for (int q = 0; q < 8; q++) {
        float dot = dotq[q];
        float dv = 0.f;
        if (lane < 16) dv = Ei / (Si + __expf(dot - mi));
        dval[q] = dv;
        float hv = (lane >= 16) ? dot : -1e30f;
#pragma unroll
        for (int off = 16; off; off >>= 1) hv = fmaxf(hv, __shfl_xor_sync(0xffffffffu, hv, off));
        float m16 = fmaxf(hv, qk[q]);
        float ev = (lane >= 16) ? __expf(dot - m16) : 0.f;
#pragma unroll
        for (int off = 16; off; off >>= 1) ev += __shfl_xor_sync(0xffffffffu, ev, off);
        float eq = __expf(qk[q] - m16);
        d16[q] = eq / (ev + eq);
    }

    // ---- v-pass: v = Wv.f ----
    float bs0 = 0.f, bq0 = 0.f, bs1 = 0.f, bq1 = 0.f;
    {
        ull v0[8], v1[8];
#pragma unroll
        for (int q = 0; q < 8; q++) { v0[q] = 0; v1[q] = 0; }
#pragma unroll
        for (int c = 0; c < 64; c += 4) {
            float4 b0 = *(const float4*)(W0 + c);
            float4 b1 = *(const float4*)(W1 + c);
            ull w0l = pk2(b0.x, b0.y), w0h = pk2(b0.z, b0.w);
            ull w1l = pk2(b1.x, b1.y), w1h = pk2(b1.z, b1.w);
#pragma unroll
            for (int q = 0; q < 8; q++) {
                float4 f = *(const float4*)&sfv[wid][q][c];
                ull fl = pk2(f.x, f.y), fh = pk2(f.z, f.w);
                v0[q] = f2fma(w0l, fl, v0[q]); v0[q] = f2fma(w0h, fh, v0[q]);
                v1[q] = f2fma(w1l, fl, v1[q]); v1[q] = f2fma(w1h, fh, v1[q]);
            }
        }

        ull oa[8];
#pragma unroll
        for (int q = 0; q < 8; q++) {
            float2 vv0 = unpk(v0[q]), vv1 = unpk(v1[q]);
            oa[q] = pk2(d16[q] * (vv0.x + vv0.y + bv0), d16[q] * (vv1.x + vv1.y + bv1));
        }
        const float2* Vb = (const float2*)&d_Vw[cls * 1024];
#pragma unroll
        for (int i = 0; i < 16; i++) {
            float2 vb = __ldg(&Vb[i * 32 + lane]);
            ull vbp = pk2(vb.x, vb.y);
#pragma unroll
            for (int q = 0; q < 8; q++) {
                float di = __shfl_sync(0xffffffffu, dval[q], i);
                oa[q] = f2fma(vbp, pk2(di, di), oa[q]);
            }
        }
#pragma unroll
        for (int q = 0; q < 8; q++) {
            if (wid * 8 + q < bn) {
                float2 o = unpk(oa[q]);
                d_x[pts[q] * 64 + lane] = o.x;
                d_x[pts[q] * 64 + lane + 32] = o.y;
                bs0 += o.x; bq0 += o.x * o.x;
                bs1 += o.y; bq1 += o.y * o.y;
            }
        }
    }

    // ---- block-level BN partial reduction (deterministic) ----
    __syncthreads();
    red[0][wid][lane] = bs0;
    red[1][wid][lane] = bq0;
    red[2][wid][lane] = bs1;
    red[3][wid][lane] = bq1;
    __syncthreads();
    if (t < 32) {
        float S0 = red[0][0][t] + red[0][1][t] + red[0][2][t] + red[0][3][t];
        float Q0 = red[1][0][t] + red[1][1][t] + red[1][2][t] + red[1][3][t];
        float S1 = red[2][0][t] + red[2][1][t] + red[2][2][t] + red[2][3][t];
        float Q1 = red[3][0][t] + red[3][1][t] + red[3][2][t] + red[3][3][t];
        d_psum[blockIdx.x * 64 + t] = S0;
        d_psq[blockIdx.x * 64 + t] = Q0;
        d_psum[blockIdx.x * 64 + 32 + t] = S1;
        d_psq[blockIdx.x * 64 + 32 + t] = Q1;
    }
}

// ------------------------- k3b: reduce bucket BN partials -> scale/shift (512 threads) -------------------------
__global__ void k3b(const float* __restrict__ gamma, const float* __restrict__ beta, int li) {
    __shared__ float ss[512], sq[512];
    int t = threadIdx.x;
    int c = t & 63, g = t >> 6;            // g in 0..7
    int nb = d_nbkt;
    float S = 0.f, Q = 0.f;
    for (int k = g; k < nb; k += 8) {
        S += d_psum[k * 64 + c];
        Q += d_psq[k * 64 + c];
    }
    ss[t] = S; sq[t] = Q;
    __syncthreads();
    if (t < 64) {
        float Sf = 0.f, Qf = 0.f;
#pragma unroll
        for (int gg = 0; gg < 8; gg++) { Sf += ss[gg * 64 + t]; Qf += sq[gg * 64 + t]; }
        float mean = Sf * (1.f / 65536.f);
        float var = Qf * (1.f / 65536.f) - mean * mean;
        float sc = gamma[li * 64 + t] / sqrtf(var + 1e-5f);
        d_scale[t] = sc;
        d_shift[t] = beta[li * 64 + t] - sc * mean;
    }
}

// ------------------------- k4: norm + relu + residual; write out slice + update fT -------------------------
__global__ void k4(float* __restrict__ out, int li) {
    int p0 = blockIdx.x * 32;
    int b = p0 >> 15, n0 = p0 & 32767;
    __shared__ float sh[64 * 33];
    int t = threadIdx.x;
#pragma unroll
    for (int k = 0; k < 8; k++) {
        int idx = t + k * 256;
        int p = idx >> 6, c = idx & 63;
        int a = (p0 + p) * 64 + c;
        float xv = d_x[a];
        float fo = d_fT[a];
        float y = fmaxf(d_scale[c] * xv + d_shift[c], 0.f);
        float fn = fo + y;
        d_fT[a] = fn;
        sh[c * 33 + p] = fn;
    }
    __syncthreads();
    int r = t >> 5, col = t & 31;
#pragma unroll
    for (int k = 0; k < 8; k++) {
        int c = r + k * 8;
        out[((size_t)(b * 192 + li * 64 + c)) * NN + n0 + col] = sh[c * 33 + col];
    }
}

// ------------------------- launch -------------------------
extern "C" void kernel_launch(void* const* d_in, const int* in_sizes, int n_in,
                              void* d_out, int out_size) {
    const float* feature = (const float*)d_in[0];
    const int*   knn     = (const int*)d_in[1];
    const float* Wq      = (const float*)d_in[2];
    const float* bq      = (const float*)d_in[3];
    const float* Wk      = (const float*)d_in[4];
    const float* bk      = (const float*)d_in[5];
    const float* Wv      = (const float*)d_in[6];
    const float* bv      = (const float*)d_in[7];
    const float* gamma   = (const float*)d_in[8];
    const float* beta    = (const float*)d_in[9];
    float* out = (float*)d_out;

    kT<<<2048, 256>>>(feature);
    k0<<<8192, 256>>>(knn);
    for (int li = 0; li < 3; li++) {
        kPre<<<128, 256>>>(Wq, bq, Wk, bk, Wv, bv, li);
        k2<<<NBLK2, 128>>>(Wv, bv, li);
        k3b<<<1, 512>>>(gamma, beta, li);
        k4<<<2048, 256>>>(out, li);
    }
}

// round 13
// speedup vs baseline: 1.2010x; 1.2010x over previous
#include <cuda_runtime.h>
#include <cstdint>

#define NB 2
#define NN 32768
#define NC 64
#define NPT (NB * NN)
#define NBLK2 2080

typedef unsigned long long ull;

__device__ __forceinline__ ull pk2(float x, float y) {
    ull r; asm("mov.b64 %0, {%1,%2};" : "=l"(r) : "f"(x), "f"(y)); return r;
}
__device__ __forceinline__ float2 unpk(ull a) {
    float2 v; asm("mov.b64 {%0,%1}, %2;" : "=f"(v.x), "=f"(v.y) : "l"(a)); return v;
}
__device__ __forceinline__ ull f2fma(ull a, ull b, ull c) {
    ull d; asm("fma.rn.f32x2 %0, %1, %2, %3;" : "=l"(d) : "l"(a), "l"(b), "l"(c)); return d;
}

// ------------------------- device scratch (no allocs) -------------------------
__device__ __align__(16) float d_fT[NPT * NC];
__device__ __align__(16) float d_x[NPT * NC];
__device__ unsigned char d_cls[NPT];
__device__ int d_seq[16 * 16];
__device__ __align__(16) float d_A[64 * 64];
__device__ float d_gvec[64];
__device__ float d_c0;
__device__ __align__(16) float d_PR[32 * 64 * 32];  // [cls][c][i32]
__device__ __align__(16) float d_Vw[32 * 16 * 64];  // [cls][i][pair] interleaved (c,c+32)
__device__ float d_pb[32 * 32];
__device__ float d_m[32 * 16];
__device__ float d_S16[32 * 16];
__device__ float d_Eii[32 * 16];
__device__ float d_psum[NBLK2 * 64];   // [bucket][c]
__device__ float d_psq[NBLK2 * 64];
__device__ float d_ps2s[64 * 64];      // stage-1 reduced [j][c]
__device__ float d_ps2q[64 * 64];
__device__ float d_scale[64];
__device__ float d_shift[64];
// sorting
__device__ int d_done;
__device__ int d_cnt[32];
__device__ int d_base[32];
__device__ int d_pos[32];
__device__ int d_ecum[33];
__device__ int d_nbkt;
__device__ int d_order[NPT];
__device__ int d_bcls[NBLK2];
__device__ int d_bstart[NBLK2];
__device__ int d_bn[NBLK2];

// ------------------------- kT: transpose feature -> point-major (+zero counters) -------------------------
__global__ void kT(const float* __restrict__ feat) {
    int bI = blockIdx.x;
    int b = bI >> 10;
    int n0 = (bI & 1023) * 32;
    __shared__ __align__(16) float sh[64 * 33];
    int t = threadIdx.x;
    if (bI == 0 && t < 32) d_cnt[t] = 0;
    if (bI == 0 && t == 32) d_done = 0;
#pragma unroll
    for (int k = 0; k < 8; k++) {
        int idx = t + k * 256;
        int c = idx >> 5, col = idx & 31;
        sh[c * 33 + col] = feat[(b * 64 + c) * NN + n0 + col];
    }
    __syncthreads();
    int p = t >> 3, c8 = (t & 7) * 8;
    float4 v0, v1;
    v0.x = sh[(c8 + 0) * 33 + p]; v0.y = sh[(c8 + 1) * 33 + p];
    v0.z = sh[(c8 + 2) * 33 + p]; v0.w = sh[(c8 + 3) * 33 + p];
    v1.x = sh[(c8 + 4) * 33 + p]; v1.y = sh[(c8 + 5) * 33 + p];
    v1.z = sh[(c8 + 6) * 33 + p]; v1.w = sh[(c8 + 7) * 33 + p];
    float* dst = &d_fT[(b * NN + n0 + p) * 64 + c8];
    *(float4*)dst = v0;
    *(float4*)(dst + 4) = v1;
}

// ------------------------- k0: argmax2 class + histogram + (last block) scan + walk sequences -------------------------
__global__ void k0(const int* __restrict__ knn) {
    int w = threadIdx.x >> 5, lane = threadIdx.x & 31;
    int pt = blockIdx.x * 8 + w;
    int b = pt >> 15, n = pt & 32767;
    __shared__ __align__(16) float selfv[8][64];
    __shared__ float simsh[8][16];
    __shared__ int h[32];
    __shared__ int shLast;
    if (threadIdx.x < 32) h[threadIdx.x] = 0;

    float2 fv = *(const float2*)&d_fT[pt * 64 + lane * 2];
    selfv[w][lane * 2] = fv.x;
    selfv[w][lane * 2 + 1] = fv.y;
    __syncthreads();

    int j = lane & 15, half = lane >> 4;
    int nb = __ldg(&knn[(b * NN + n) * 16 + j]);
    const float* nrow = &d_fT[(b * NN + nb) * 64 + half * 32];
    const float* srow = &selfv[w][half * 32];
    float part = 0.f;
#pragma unroll
    for (int c = 0; c < 32; c += 4) {
        float4 nv = *(const float4*)(nrow + c);
        float4 sv = *(const float4*)(srow + c);
        part += nv.x * sv.x + nv.y * sv.y + nv.z * sv.z + nv.w * sv.w;
    }
    float sim = part + __shfl_xor_sync(0xffffffffu, part, 16);
    if (half == 0) simsh[w][j] = sim;
    __syncwarp();

    if (lane == 0) {
        float v1 = -1e30f; int i1 = 0;
        for (int jj = 0; jj < 16; jj++) {
            float v = simsh[w][jj];
            if (v > v1) { v1 = v; i1 = jj; }
        }
        float v2 = -1e30f; int i2 = 0;
        for (int jj = 0; jj < 16; jj++) {
            if (jj == i1) continue;
            float v = simsh[w][jj];
            if (v > v2) { v2 = v; i2 = jj; }
        }
        d_cls[pt] = (unsigned char)i2;
        atomicAdd(&h[(b << 4) | i2], 1);
    }
    __syncthreads();
    if (threadIdx.x < 32 && h[threadIdx.x]) atomicAdd(&d_cnt[threadIdx.x], h[threadIdx.x]);

    // ---- last-block-done: run scan + walk sequences ----
    __threadfence();
    __syncthreads();
    if (threadIdx.x == 0)
        shLast = (atomicAdd(&d_done, 1) == (int)gridDim.x - 1) ? 1 : 0;
    __syncthreads();
    if (shLast && threadIdx.x < 32) {
        int t = threadIdx.x;
        int cnt = atomicAdd(&d_cnt[t], 0);    // L2-coherent read
        int x = cnt;
#pragma unroll
        for (int off = 1; off < 32; off <<= 1) {
            int y = __shfl_up_sync(0xffffffffu, x, off);
            if (t >= off) x += y;
        }
        int ex = x - cnt;
        d_base[t] = ex;
        d_pos[t] = ex;
        int ent = (cnt + 31) >> 5;
        int z = ent;
#pragma unroll
        for (int off = 1; off < 32; off <<= 1) {
            int y = __shfl_up_sync(0xffffffffu, z, off);
            if (t >= off) z += y;
        }
        int eex = z - ent;
        d_ecum[t] = eex;
        if (t == 31) { d_ecum[32] = z; d_nbkt = z; }
        if (t < 16) {
            int cur = t;
            d_seq[t * 16] = t;
            for (int s = 1; s < 16; s++) {
                cur = (int)__ldcg(&d_cls[cur]);
                d_seq[t * 16 + s] = cur;
            }
        }
    }
}

// ------------------------- kPre: blocks 0-31 class tables, 32-63 A matrix + bucket fill, 64-127 scatter (li==0) -------------------------
__global__ void __launch_bounds__(256) kPre(const float* __restrict__ Wq, const float* __restrict__ bq,
                                            const float* __restrict__ Wk, const float* __restrict__ bk,
                                            const float* __restrict__ Wv, const float* __restrict__ bv, int li) {
    const float* wq = Wq + li * 4096;
    const float* wk = Wk + li * 4096;
    const float* wv = Wv + li * 4096;
    const float* bqv = bq + li * 64;
    const float* bkv = bk + li * 64;
    const float* bvv = bv + li * 64;
    int t = threadIdx.x;

    if (blockIdx.x >= 64) {
        // ---- scatter with block-aggregated atomics (only layer 0) ----
        if (li != 0) return;
        __shared__ int hcnt[32], hbase[32];
        if (t < 32) hcnt[t] = 0;
        __syncthreads();
        int sb = blockIdx.x - 64;
        int mycls[4], myrank[4];
#pragma unroll
        for (int k = 0; k < 4; k++) {
            int pt = sb * 1024 + k * 256 + t;
            int cls = ((pt >> 15) << 4) | (int)d_cls[pt];
            mycls[k] = cls;
            myrank[k] = atomicAdd(&hcnt[cls], 1);
        }
        __syncthreads();
        if (t < 32 && hcnt[t]) hbase[t] = atomicAdd(&d_pos[t], hcnt[t]);
        __syncthreads();
#pragma unroll
        for (int k = 0; k < 4; k++) {
            int pt = sb * 1024 + k * 256 + t;
            d_order[hbase[mycls[k]] + myrank[k]] = pt;
        }
        return;
    }

    __shared__ __align__(16) float shA[64 * 68];
    __shared__ __align__(16) float shB[64 * 68];
    __shared__ float Wf[1024], Qw[1024], Kw[1024];
    __shared__ float simm[256];

    if (blockIdx.x >= 32) {
        // ---- bucket table fill (65 entries per block) ----
        int nbkt = d_nbkt;
        int ebase = (blockIdx.x - 32) * 65;
        if (t < 65) {
            int e = ebase + t;
            if (e < NBLK2) {
                if (e < nbkt) {
                    int c = 0;
                    while (c < 31 && d_ecum[c + 1] <= e) c++;
                    int local = e - d_ecum[c];
                    int cnt = d_cnt[c];
                    d_bcls[e] = c;
                    d_bstart[e] = d_base[c] + local * 32;
                    int rem = cnt - local * 32;
                    d_bn[e] = rem < 32 ? rem : 32;
                } else {
                    d_bcls[e] = -1;
                }
            }
        }
        // ---- A = Wq^T Wk ----
        for (int idx = t; idx < 4096; idx += 256) {
            shA[idx] = __ldg(&wq[idx]);
            shB[idx] = __ldg(&wk[idx]);
        }
        __syncthreads();
        int base = (blockIdx.x - 32) * 128;
        if (t < 128) {
            int e = base + t;
            int c = e >> 6, cp = e & 63;
            float a = 0.f;
#pragma unroll 8
            for (int d = 0; d < 64; d++) a += shA[d * 64 + c] * shB[d * 64 + cp];
            d_A[e] = a;
        }
        if (blockIdx.x == 32) {
            if (t >= 128 && t < 192) {
                int c = t - 128;
                float g = 0.f;
                for (int d = 0; d < 64; d++) g += __ldg(&bqv[d]) * shB[d * 64 + c] + __ldg(&bkv[d]) * shA[d * 64 + c];
                d_gvec[c] = g;
            }
            if (t == 255) {
                float c0 = 0.f;
                for (int d = 0; d < 64; d++) c0 += __ldg(&bqv[d]) * __ldg(&bkv[d]);
                d_c0 = c0;
            }
        }
        return;
    }

    int cls = blockIdx.x;
    int b = cls >> 4, s = cls & 15;

    for (int idx = t; idx < 4096; idx += 256) {
        int d = idx >> 6, c = idx & 63;
        shA[c * 68 + d] = __ldg(&wq[idx]);
        shB[c * 68 + d] = __ldg(&wk[idx]);
    }
    for (int idx = t; idx < 1024; idx += 256) {
        int i = idx >> 6, c = idx & 63;
        int p = d_seq[s * 16 + i];
        Wf[idx] = d_fT[(b * NN + p) * 64 + c];
    }
    __syncthreads();

    for (int idx = t; idx < 1024; idx += 256) {
        int i = idx >> 6, d = idx & 63;
        float aq = __ldg(&bqv[d]), ak = __ldg(&bkv[d]), av = __ldg(&bvv[d]);
#pragma unroll
        for (int c = 0; c < 64; c += 4) {
            float4 q4 = __ldg((const float4*)&wq[d * 64 + c]);
            float4 k4 = __ldg((const float4*)&wk[d * 64 + c]);
            float4 v4 = __ldg((const float4*)&wv[d * 64 + c]);
            float4 wf = *(const float4*)&Wf[i * 64 + c];
            aq += q4.x * wf.x + q4.y * wf.y + q4.z * wf.z + q4.w * wf.w;
            ak += k4.x * wf.x + k4.y * wf.y + k4.z * wf.z + k4.w * wf.w;
            av += v4.x * wf.x + v4.y * wf.y + v4.z * wf.z + v4.w * wf.w;
        }
        Qw[idx] = aq;
        Kw[idx] = ak;
        int pos = (d < 32) ? (2 * d) : (2 * (d - 32) + 1);
        d_Vw[cls * 1024 + i * 64 + pos] = av;
    }
    __syncthreads();

    for (int idx = t; idx < 1024; idx += 256) {
        int i = idx >> 6, c = idx & 63;
        float ap = 0.f, ar = 0.f;
#pragma unroll
        for (int d = 0; d < 64; d += 4) {
            float4 kk = *(const float4*)&shB[c * 68 + d];
            float4 qq = *(const float4*)&shA[c * 68 + d];
            float4 qw = *(const float4*)&Qw[i * 64 + d];
            float4 kw = *(const float4*)&Kw[i * 64 + d];
            ap += qw.x * kk.x + qw.y * kk.y + qw.z * kk.z + qw.w * kk.w;
            ar += kw.x * qq.x + kw.y * qq.y + kw.z * qq.z + kw.w * qq.w;
        }
        d_PR[cls * 2048 + c * 32 + i] = ap;
        d_PR[cls * 2048 + c * 32 + 16 + i] = ar;
    }
    if (t < 32) {
        int i = t & 15;
        float acc = 0.f;
        if (t < 16) { for (int d = 0; d < 64; d++) acc += Qw[i * 64 + d] * __ldg(&bkv[d]); }
        else        { for (int d = 0; d < 64; d++) acc += Kw[i * 64 + d] * __ldg(&bqv[d]); }
        d_pb[cls * 32 + t] = acc;
    }
    {
        int i = t >> 4, jj = t & 15;
        float a = 0.f;
        for (int d = 0; d < 64; d++) a += Qw[i * 64 + d] * Kw[jj * 64 + d];
        simm[t] = a;
    }
    __syncthreads();
    if (t < 16) {
        float m = -1e30f;
        for (int jj = 0; jj < 16; jj++) m = fmaxf(m, simm[t * 16 + jj]);
        float S = 0.f;
        for (int jj = 0; jj < 16; jj++) S += __expf(simm[t * 16 + jj] - m);
        d_m[cls * 16 + t] = m;
        d_S16[cls * 16 + t] = S;
        d_Eii[cls * 16 + t] = __expf(simm[t * 16 + t] - m);
    }
}

// ------------------------- k2: q=8, two-pass matvec, fused BN partials -------------------------
__global__ void __launch_bounds__(128, 4) k2(const float* __restrict__ Wv,
                                             const float* __restrict__ bv, int li) {
    int cls = __ldg(&d_bcls[blockIdx.x]);
    if (cls < 0) return;
    int bstart = __ldg(&d_bstart[blockIdx.x]);
    int bn = __ldg(&d_bn[blockIdx.x]);

    __shared__ __align__(16) float As[64 * 68];
    __shared__ __align__(16) float Ws[64 * 68];
    __shared__ __align__(16) float sfv[4][8][64];
    __shared__ float red[4][4][32];
    int t = threadIdx.x;
    const float* wv = Wv + li * 4096;

    for (int idx = t; idx < 4096; idx += 128) {
        int r = idx >> 6, c = idx & 63;
        As[r * 68 + c] = d_A[idx];
        Ws[r * 68 + c] = __ldg(&wv[idx]);
    }
    __syncthreads();

    int wid = t >> 5, lane = t & 31;

    int pts[8];
#pragma unroll
    for (int q = 0; q < 8; q++) {
        int idx = wid * 8 + q;
        int src = bstart + (idx < bn ? idx : 0);
        int pt = __ldg(&d_order[src]);
        pts[q] = pt;
        float2 fv = *(const float2*)&d_fT[pt * 64 + lane * 2];
        sfv[wid][q][lane * 2] = fv.x;
        sfv[wid][q][lane * 2 + 1] = fv.y;
    }
    __syncwarp();

    float pbl = __ldg(&d_pb[cls * 32 + lane]);
    float mi = 0.f, Si = 0.f, Ei = 0.f;
    if (lane < 16) {
        mi = __ldg(&d_m[cls * 16 + lane]);
        Si = __ldg(&d_S16[cls * 16 + lane]);
        Ei = __ldg(&d_Eii[cls * 16 + lane]);
    }
    float gl0 = __ldg(&d_gvec[lane]);
    float gl1 = __ldg(&d_gvec[lane + 32]);
    float c0v = d_c0;
    float bv0 = __ldg(&bv[li * 64 + lane]);
    float bv1 = __ldg(&bv[li * 64 + lane + 32]);

    const float* A0 = &As[lane * 68];
    const float* A1 = &As[(lane + 32) * 68];
    const float* W0 = &Ws[lane * 68];
    const float* W1 = &Ws[(lane + 32) * 68];

    // ---- u-pass: u = A.f ----
    float qk[8];
    {
        ull u0[8], u1[8];
#pragma unroll
        for (int q = 0; q < 8; q++) { u0[q] = 0; u1[q] = 0; }
#pragma unroll
        for (int c = 0; c < 64; c += 4) {
            float4 a0 = *(const float4*)(A0 + c);
            float4 a1 = *(const float4*)(A1 + c);
            ull a0l = pk2(a0.x, a0.y), a0h = pk2(a0.z, a0.w);
            ull a1l = pk2(a1.x, a1.y), a1h = pk2(a1.z, a1.w);
#pragma unroll
            for (int q = 0; q < 8; q++) {
                float4 f = *(const float4*)&sfv[wid][q][c];
                ull fl = pk2(f.x, f.y), fh = pk2(f.z, f.w);
                u0[q] = f2fma(a0l, fl, u0[q]); u0[q] = f2fma(a0h, fh, u0[q]);
                u1[q] = f2fma(a1l, fl, u1[q]); u1[q] = f2fma(a1h, fh, u1[q]);
            }
        }
#pragma unroll
        for (int q = 0; q < 8; q++) {
            float2 uu0 = unpk(u0[q]), uu1 = unpk(u1[q]);
            float fl0 = sfv[wid][q][lane];
            float fl1 = sfv[wid][q][lane + 32];
            float part = (uu0.x + uu0.y + gl0) * fl0 + (uu1.x + uu1.y + gl1) * fl1;
#pragma unroll
            for (int off = 16; off; off >>= 1) part += __shfl_xor_sync(0xffffffffu, part, off);
            qk[q] = part + c0v;
        }
    }

    // ---- cross terms + softmax diagonals ----
    const float* PRb = &d_PR[cls * 2048];
    float dotq[8];
#pragma unroll
    for (int q = 0; q < 8; q++) dotq[q] = pbl;
#pragma unroll 4
    for (int c = 0; c < 64; c += 4) {
        float p0 = __ldg(&PRb[c * 32 + lane]);
        float p1 = __ldg(&PRb[(c + 1) * 32 + lane]);
        float p2 = __ldg(&PRb[(c + 2) * 32 + lane]);
        float p3 = __ldg(&PRb[(c + 3) * 32 + lane]);
#pragma unroll
        for (int q = 0; q < 8; q++) {
            float4 f = *(const float4*)&sfv[wid][q][c];
            dotq[q] += p0 * f.x + p1 * f.y + p2 * f.z + p3 * f.w;
        }
    }

    float dval[8], d16[8];
#pragma unroll
    for (int q = 0; q < 8; q++) {
        float dot = dotq[q];
        float dv = 0.f;
        if (lane < 16) dv = Ei / (Si + __expf(dot - mi));
        dval[q] = dv;
        float hv = (lane >= 16) ? dot : -1e30f;
#pragma unroll
        for (int off = 16; off; off >>= 1) hv = fmaxf(hv, __shfl_xor_sync(0xffffffffu, hv, off));
        float m16 = fmaxf(hv, qk[q]);
        float ev = (lane >= 16) ? __expf(dot - m16) : 0.f;
#pragma unroll
        for (int off = 16; off; off >>= 1) ev += __shfl_xor_sync(0xffffffffu, ev, off);
        float eq = __expf(qk[q] - m16);
        d16[q] = eq / (ev + eq);
    }

    // ---- v-pass: v = Wv.f ----
    float bs0 = 0.f, bq0 = 0.f, bs1 = 0.f, bq1 = 0.f;
    {
        ull v0[8], v1[8];
#pragma unroll
        for (int q = 0; q < 8; q++) { v0[q] = 0; v1[q] = 0; }
#pragma unroll
        for (int c = 0; c < 64; c += 4) {
            float4 b0 = *(const float4*)(W0 + c);
            float4 b1 = *(const float4*)(W1 + c);
            ull w0l = pk2(b0.x, b0.y), w0h = pk2(b0.z, b0.w);
            ull w1l = pk2(b1.x, b1.y), w1h = pk2(b1.z, b1.w);
#pragma unroll
            for (int q = 0; q < 8; q++) {
                float4 f = *(const float4*)&sfv[wid][q][c];
                ull fl = pk2(f.x, f.y), fh = pk2(f.z, f.w);
                v0[q] = f2fma(w0l, fl, v0[q]); v0[q] = f2fma(w0h, fh, v0[q]);
                v1[q] = f2fma(w1l, fl, v1[q]); v1[q] = f2fma(w1h, fh, v1[q]);
            }
        }

        ull oa[8];
#pragma unroll
        for (int q = 0; q < 8; q++) {
            float2 vv0 = unpk(v0[q]), vv1 = unpk(v1[q]);
            oa[q] = pk2(d16[q] * (vv0.x + vv0.y + bv0), d16[q] * (vv1.x + vv1.y + bv1));
        }
        const float2* Vb = (const float2*)&d_Vw[cls * 1024];
#pragma unroll
        for (int i = 0; i < 16; i++) {
            float2 vb = __ldg(&Vb[i * 32 + lane]);
            ull vbp = pk2(vb.x, vb.y);
#pragma unroll
            for (int q = 0; q < 8; q++) {
                float di = __shfl_sync(0xffffffffu, dval[q], i);
                oa[q] = f2fma(vbp, pk2(di, di), oa[q]);
            }
        }
#pragma unroll
        for (int q = 0; q < 8; q++) {
            if (wid * 8 + q < bn) {
                float2 o = unpk(oa[q]);
                d_x[pts[q] * 64 + lane] = o.x;
                d_x[pts[q] * 64 + lane + 32] = o.y;
                bs0 += o.x; bq0 += o.x * o.x;
                bs1 += o.y; bq1 += o.y * o.y;
            }
        }
    }

    // ---- block-level BN partial reduction (deterministic) ----
    __syncthreads();
    red[0][wid][lane] = bs0;
    red[1][wid][lane] = bq0;
    red[2][wid][lane] = bs1;
    red[3][wid][lane] = bq1;
    __syncthreads();
    if (t < 32) {
        float S0 = red[0][0][t] + red[0][1][t] + red[0][2][t] + red[0][3][t];
        float Q0 = red[1][0][t] + red[1][1][t] + red[1][2][t] + red[1][3][t];
        float S1 = red[2][0][t] + red[2][1][t] + red[2][2][t] + red[2][3][t];
        float Q1 = red[3][0][t] + red[3][1][t] + red[3][2][t] + red[3][3][t];
        d_psum[blockIdx.x * 64 + t] = S0;
        d_psq[blockIdx.x * 64 + t] = Q0;
        d_psum[blockIdx.x * 64 + 32 + t] = S1;
        d_psq[blockIdx.x * 64 + 32 + t] = Q1;
    }
}

// ------------------------- k3b1: stage-1 BN reduce (64 blocks) -------------------------
__global__ void k3b1() {
    __shared__ float ss[256], sq[256];
    int t = threadIdx.x;
    int c = t & 63, g = t >> 6;            // g in 0..3
    int j = blockIdx.x;                    // 0..63
    int nb = d_nbkt;
    float S = 0.f, Q = 0.f;
    for (int k = j + (g * 64); k < nb; k += 256) {
        S += d_psum[k * 64 + c];
        Q += d_psq[k * 64 + c];
    }
    ss[t] = S; sq[t] = Q;
    __syncthreads();
    if (t < 64) {
        float Sf = ss[t] + ss[t + 64] + ss[t + 128] + ss[t + 192];
        float Qf = sq[t] + sq[t + 64] + sq[t + 128] + sq[t + 192];
        d_ps2s[j * 64 + t] = Sf;
        d_ps2q[j * 64 + t] = Qf;
    }
}

// ------------------------- k3b2: finalize BN scale/shift -------------------------
__global__ void k3b2(const float* __restrict__ gamma, const float* __restrict__ beta, int li) {
    __shared__ float ss[512], sq[512];
    int t = threadIdx.x;
    int c = t & 63, g = t >> 6;            // g in 0..7
    float S = 0.f, Q = 0.f;
    for (int j = g; j < 64; j += 8) {
        S += d_ps2s[j * 64 + c];
        Q += d_ps2q[j * 64 + c];
    }
    ss[t] = S; sq[t] = Q;
    __syncthreads();
    if (t < 64) {
        float Sf = 0.f, Qf = 0.f;
#pragma unroll
        for (int gg = 0; gg < 8; gg++) { Sf += ss[gg * 64 + t]; Qf += sq[gg * 64 + t]; }
        float mean = Sf * (1.f / 65536.f);
        float var = Qf * (1.f / 65536.f) - mean * mean;
        float sc = gamma[li * 64 + t] / sqrtf(var + 1e-5f);
        d_scale[t] = sc;
        d_shift[t] = beta[li * 64 + t] - sc * mean;
    }
}

// ------------------------- k4: norm + relu + residual; write out slice + update fT -------------------------
__global__ void k4(float* __restrict__ out, int li) {
    int p0 = blockIdx.x * 32;
    int b = p0 >> 15, n0 = p0 & 32767;
    __shared__ float sh[64 * 33];
    int t = threadIdx.x;
#pragma unroll
    for (int k = 0; k < 8; k++) {
        int idx = t + k * 256;
        int p = idx >> 6, c = idx & 63;
        int a = (p0 + p) * 64 + c;
        float xv = d_x[a];
        float fo = d_fT[a];
        float y = fmaxf(d_scale[c] * xv + d_shift[c], 0.f);
        float fn = fo + y;
        d_fT[a] = fn;
        sh[c * 33 + p] = fn;
    }
    __syncthreads();
    int r = t >> 5, col = t & 31;
#pragma unroll
    for (int k = 0; k < 8; k++) {
        int c = r + k * 8;
        out[((size_t)(b * 192 + li * 64 + c)) * NN + n0 + col] = sh[c * 33 + col];
    }
}

// ------------------------- launch -------------------------
extern "C" void kernel_launch(void* const* d_in, const int* in_sizes, int n_in,
                              void* d_out, int out_size) {
    const float* feature = (const float*)d_in[0];
    const int*   knn     = (const int*)d_in[1];
    const float* Wq      = (const float*)d_in[2];
    const float* bq      = (const float*)d_in[3];
    const float* Wk      = (const float*)d_in[4];
    const float* bk      = (const float*)d_in[5];
    const float* Wv      = (const float*)d_in[6];
    const float* bv      = (const float*)d_in[7];
    const float* gamma   = (const float*)d_in[8];
    const float* beta    = (const float*)d_in[9];
    float* out = (float*)d_out;

    kT<<<2048, 256>>>(feature);
    k0<<<8192, 256>>>(knn);
    for (int li = 0; li < 3; li++) {
        kPre<<<128, 256>>>(Wq, bq, Wk, bk, Wv, bv, li);
        k2<<<NBLK2, 128>>>(Wv, bv, li);
        k3b1<<<64, 256>>>();
        k3b2<<<1, 512>>>(gamma, beta, li);
        k4<<<2048, 256>>>(out, li);
    }
}